// round 8
// baseline (speedup 1.0000x reference)
#include <cuda_runtime.h>
#include <math.h>

#define TT 1024
#define BB 512
#define KK 128
#define GG 2      // batches per fwd block
#define NFWD (BB / GG)   // 256 fwd CTAs
#define NPATH 40         // path CTAs (fill free occupancy slots: 296 = 148*2)
#define NCTA (NFWD + NPATH)

// ---- packed f32x2 helpers (sm_103a), NON-volatile so ptxas can schedule ----
__device__ __forceinline__ unsigned long long pk2(float a, float b) {
    unsigned long long r;
    asm("mov.b64 %0, {%1,%2};" : "=l"(r) : "f"(a), "f"(b));
    return r;
}
__device__ __forceinline__ void fma2(unsigned long long& d, unsigned long long a, unsigned long long b) {
    asm("fma.rn.f32x2 %0, %1, %2, %0;" : "+l"(d) : "l"(a), "l"(b));
}
__device__ __forceinline__ void upk2(unsigned long long v, float& a, float& b) {
    asm("mov.b64 {%0,%1}, %2;" : "=f"(a), "=f"(b) : "l"(v));
}

__device__ float g_negLogZ[BB];
__device__ float g_path[BB];
__device__ int   g_done = 0;    // last-CTA detector; reset by the last CTA each launch

__global__ void __launch_bounds__(128, 2) crf_kernel(
    const float* __restrict__ em,      // [T,B,K]
    const int*   __restrict__ tags,    // [T,B]
    const float* __restrict__ mask,    // [T,B]
    const float* __restrict__ startT,  // [K]
    const float* __restrict__ trans,   // [K,K]
    const float* __restrict__ endT,    // [K]
    float* __restrict__ out)
{
    const int tid = threadIdx.x;

    if (blockIdx.x < NFWD) {
        // ================= forward recurrence CTA =================
        __shared__ alignas(16) float pv[2][GG][KK];
        __shared__ float wred[4][GG];

        const int j    = tid;
        const int warp = j >> 5;
        const int lane = j & 31;
        const int b0   = blockIdx.x * GG;

        // E column pre-packed over i
        unsigned long long epk[KK / 2];
#pragma unroll
        for (int m = 0; m < KK / 2; m++) {
            epk[m] = pk2(__expf(trans[(2 * m) * KK + j]),
                         __expf(trans[(2 * m + 1) * KK + j]));
        }

        float u[GG];
        int   Ce[GG];
        const float sj = startT[j];
#pragma unroll
        for (int g = 0; g < GG; g++) {
            u[g]  = __expf(sj + em[(b0 + g) * KK + j]);
            Ce[g] = 0;
            pv[1][g][j] = u[g];
        }
        __syncthreads();

        // 2-deep register prefetch pipeline for em/mask
        float ecur[GG], enext[GG], mcur[GG], mnext[GG];
#pragma unroll
        for (int g = 0; g < GG; g++) {
            ecur[g]  = __ldg(&em[(1 * BB + b0 + g) * KK + j]);
            mcur[g]  = __ldg(&mask[1 * BB + b0 + g]);
            enext[g] = __ldg(&em[(2 * BB + b0 + g) * KK + j]);
            mnext[g] = __ldg(&mask[2 * BB + b0 + g]);
        }

#pragma unroll 2
        for (int t = 1; t < TT; t++) {
            const int r = t & 1, w = r ^ 1;

            // kick off loads for t+2 immediately after the barrier
            const int tp = (t + 2 < TT) ? (t + 2) : (TT - 1);
            float epre[GG], mpre[GG];
#pragma unroll
            for (int g = 0; g < GG; g++) {
                epre[g] = __ldg(&em[(tp * BB + b0 + g) * KK + j]);
                mpre[g] = __ldg(&mask[tp * BB + b0 + g]);
            }

            // matvec: S[g] = sum_i u_prev[g][i] * E[i][j]
            unsigned long long acc0[GG], acc1[GG];
#pragma unroll
            for (int g = 0; g < GG; g++) { acc0[g] = 0ull; acc1[g] = 0ull; }
#pragma unroll
            for (int k = 0; k < KK / 4; k++) {
#pragma unroll
                for (int g = 0; g < GG; g++) {
                    const ulonglong2 q = *(const ulonglong2*)&pv[r][g][4 * k];
                    fma2(acc0[g], epk[2 * k],     q.x);
                    fma2(acc1[g], epk[2 * k + 1], q.y);
                }
            }

#pragma unroll
            for (int g = 0; g < GG; g++) {
                float a, b, c, d;
                upk2(acc0[g], a, b);
                upk2(acc1[g], c, d);
                float S  = (a + b) + (c + d);
                float un = __expf(ecur[g]) * S;
                u[g] = (mcur[g] != 0.0f) ? un : u[g];
            }

            // rotate prefetch pipeline
#pragma unroll
            for (int g = 0; g < GG; g++) {
                ecur[g]  = enext[g];  mcur[g]  = mnext[g];
                enext[g] = epre[g];   mnext[g] = mpre[g];
            }

            // exact power-of-2 rescale every 8 steps
            if ((t & 7) == 0) {
                float wm[GG];
#pragma unroll
                for (int g = 0; g < GG; g++) {
                    float v = u[g];
                    for (int o = 16; o; o >>= 1) v = fmaxf(v, __shfl_xor_sync(0xffffffffu, v, o));
                    wm[g] = v;
                }
                if (lane == 0) {
#pragma unroll
                    for (int g = 0; g < GG; g++) wred[warp][g] = wm[g];
                }
                __syncthreads();
#pragma unroll
                for (int g = 0; g < GG; g++) {
                    float m = fmaxf(fmaxf(wred[0][g], wred[1][g]),
                                    fmaxf(wred[2][g], wred[3][g]));
                    int e   = ilogbf(m);
                    float s = __int_as_float((unsigned)(127 - e) << 23);
                    u[g]  *= s;
                    Ce[g] += e;
                }
            }

#pragma unroll
            for (int g = 0; g < GG; g++) pv[w][g][j] = u[g];
            __syncthreads();
        }

        // finalize -logZ for this CTA's batches
        const float ezj = __expf(endT[j]);
#pragma unroll
        for (int g = 0; g < GG; g++) {
            float z = u[g] * ezj;
            for (int o = 16; o; o >>= 1) z += __shfl_xor_sync(0xffffffffu, z, o);
            if (lane == 0) wred[warp][g] = z;
        }
        __syncthreads();
        if (j < GG) {
            const int g = j;
            float zsum  = wred[0][g] + wred[1][g] + wred[2][g] + wred[3][g];
            double logZ = (double)Ce[g] * 0.6931471805599453 + log((double)zsum);
            g_negLogZ[b0 + g] = (float)(-logZ);
        }
        __syncthreads();
    } else {
        // ================= gold-path gather CTA =================
        __shared__ float sacc[4], smsum[4];
        const int warp = tid >> 5, lane = tid & 31;
        const int pb = blockIdx.x - NFWD;
        for (int b = pb; b < BB; b += NPATH) {
            float acc = 0.0f, msum = 0.0f;
            for (int t = tid; t < TT; t += 128) {
                int   tg = tags[t * BB + b];
                float m  = mask[t * BB + b];
                acc  += em[(t * BB + b) * KK + tg] * m;
                msum += m;
                if (t > 0) {
                    int tp2 = tags[(t - 1) * BB + b];
                    acc += trans[tp2 * KK + tg] * m;
                }
            }
            for (int o = 16; o; o >>= 1) {
                acc  += __shfl_xor_sync(0xffffffffu, acc, o);
                msum += __shfl_xor_sync(0xffffffffu, msum, o);
            }
            if (lane == 0) { sacc[warp] = acc; smsum[warp] = msum; }
            __syncthreads();
            if (tid == 0) {
                float a  = sacc[0] + sacc[1] + sacc[2] + sacc[3];
                float ms = smsum[0] + smsum[1] + smsum[2] + smsum[3];
                int cnt = (int)(ms + 0.5f); if (cnt < 1) cnt = 1;
                a += startT[tags[b]] + endT[tags[(cnt - 1) * BB + b]];
                g_path[b] = a;
            }
            __syncthreads();
        }
    }

    // ================= last-CTA final reduction =================
    __shared__ int amLast;
    __shared__ float rsum[4];
    __threadfence();
    if (tid == 0) {
        int old = atomicAdd(&g_done, 1);
        amLast = (old == NCTA - 1);
    }
    __syncthreads();
    if (amLast) {
        __threadfence();
        const int warp = tid >> 5, lane = tid & 31;
        float s = 0.0f;
        for (int b = tid; b < BB; b += 128) s += g_path[b] + g_negLogZ[b];
        for (int o = 16; o; o >>= 1) s += __shfl_xor_sync(0xffffffffu, s, o);
        if (lane == 0) rsum[warp] = s;
        __syncthreads();
        if (tid == 0) {
            out[0] = rsum[0] + rsum[1] + rsum[2] + rsum[3];
            __threadfence();
            g_done = 0;   // reset for next graph replay
        }
    }
}

extern "C" void kernel_launch(void* const* d_in, const int* in_sizes, int n_in,
                              void* d_out, int out_size) {
    const float* em     = (const float*)d_in[0];
    const int*   tags   = (const int*)  d_in[1];
    const float* mask   = (const float*)d_in[2];
    const float* startT = (const float*)d_in[3];
    const float* trans  = (const float*)d_in[4];
    const float* endT   = (const float*)d_in[5];
    float* out = (float*)d_out;

    crf_kernel<<<NCTA, KK>>>(em, tags, mask, startT, trans, endT, out);
}

// round 9
// speedup vs baseline: 1.8506x; 1.8506x over previous
#include <cuda_runtime.h>
#include <cuda_bf16.h>
#include <math.h>

#define TT 1024
#define BB 512
#define KK 128
#define GG 2   // batches per block, packed in bf16x2 lanes

__device__ float g_negLogZ[BB];   // -logZ per batch (fwd writes, path reads)

// ---- forward recurrence: scaled linear domain, bf16x2 matvec (lanes = batches) ----
// grid = BB/GG = 256 blocks, 128 threads, 2 CTAs/SM.
__global__ void __launch_bounds__(128, 2) crf_fwd_kernel(
    const float* __restrict__ em,      // [T,B,K]
    const float* __restrict__ mask,    // [T,B]
    const float* __restrict__ startT,  // [K]
    const float* __restrict__ trans,   // [K,K]
    const float* __restrict__ endT,    // [K]
    float* __restrict__ out)
{
    __shared__ alignas(16) __nv_bfloat162 pv[2][KK];  // [buf][i] -> (u_g0, u_g1)
    __shared__ float wred[4][GG];

    const int j    = threadIdx.x;   // tag column owned by this thread
    const int warp = j >> 5;
    const int lane = j & 31;
    const int b0   = blockIdx.x * GG;

    if (blockIdx.x == 0 && j == 0) out[0] = 0.0f;  // zero for launch-2 atomics

    // E column, duplicated into both bf16 lanes: epk[i] = (E[i][j], E[i][j])
    __nv_bfloat162 epk[KK];
#pragma unroll
    for (int i = 0; i < KK; i++) {
        epk[i] = __float2bfloat162_rn(__expf(trans[i * KK + j]));
    }

    float u[GG];     // fp32 master state for column j
    int   Ce[GG];    // exact power-of-2 scale exponent
    const float sj = startT[j];
#pragma unroll
    for (int g = 0; g < GG; g++) {
        u[g]  = __expf(sj + em[(b0 + g) * KK + j]);
        Ce[g] = 0;
    }
    pv[1][j] = __floats2bfloat162_rn(u[0], u[1]);   // step t=1 reads buffer 1
    __syncthreads();

    // 2-deep register prefetch pipeline for em/mask
    float ecur[GG], enext[GG], mcur[GG], mnext[GG];
#pragma unroll
    for (int g = 0; g < GG; g++) {
        ecur[g]  = __ldg(&em[(1 * BB + b0 + g) * KK + j]);
        mcur[g]  = __ldg(&mask[1 * BB + b0 + g]);
        enext[g] = __ldg(&em[(2 * BB + b0 + g) * KK + j]);
        mnext[g] = __ldg(&mask[2 * BB + b0 + g]);
    }

    for (int t = 1; t < TT; t++) {
        const int r = t & 1, w = r ^ 1;

        // kick off loads for t+2 (clamped; tail values discarded)
        const int tp = (t + 2 < TT) ? (t + 2) : (TT - 1);
        float epre[GG], mpre[GG];
#pragma unroll
        for (int g = 0; g < GG; g++) {
            epre[g] = __ldg(&em[(tp * BB + b0 + g) * KK + j]);
            mpre[g] = __ldg(&mask[tp * BB + b0 + g]);
        }

        // matvec in bf16x2: lanes carry the two batches; 4 independent acc chains
        __nv_bfloat162 a0 = __float2bfloat162_rn(0.0f);
        __nv_bfloat162 a1 = a0, a2 = a0, a3 = a0;
#pragma unroll
        for (int k = 0; k < KK / 4; k++) {
            const uint4 q = *(const uint4*)&pv[r][4 * k];   // LDS.128 broadcast: 4 i's
            a0 = __hfma2(epk[4 * k],     *(const __nv_bfloat162*)&q.x, a0);
            a1 = __hfma2(epk[4 * k + 1], *(const __nv_bfloat162*)&q.y, a1);
            a2 = __hfma2(epk[4 * k + 2], *(const __nv_bfloat162*)&q.z, a2);
            a3 = __hfma2(epk[4 * k + 3], *(const __nv_bfloat162*)&q.w, a3);
        }
        const __nv_bfloat162 s2 = __hadd2(__hadd2(a0, a1), __hadd2(a2, a3));
        const float S0 = __low2float(s2);
        const float S1 = __high2float(s2);

        {
            float un0 = __expf(ecur[0]) * S0;
            float un1 = __expf(ecur[1]) * S1;
            u[0] = (mcur[0] != 0.0f) ? un0 : u[0];
            u[1] = (mcur[1] != 0.0f) ? un1 : u[1];
        }

        // rotate prefetch pipeline
#pragma unroll
        for (int g = 0; g < GG; g++) {
            ecur[g]  = enext[g];  mcur[g]  = mnext[g];
            enext[g] = epre[g];   mnext[g] = mpre[g];
        }

        // exact power-of-2 rescale every 8 steps (fp32 master; bf16 range = fp32 range)
        if ((t & 7) == 0) {
            float wm[GG];
#pragma unroll
            for (int g = 0; g < GG; g++) {
                float v = u[g];
                for (int o = 16; o; o >>= 1) v = fmaxf(v, __shfl_xor_sync(0xffffffffu, v, o));
                wm[g] = v;
            }
            if (lane == 0) {
#pragma unroll
                for (int g = 0; g < GG; g++) wred[warp][g] = wm[g];
            }
            __syncthreads();
#pragma unroll
            for (int g = 0; g < GG; g++) {
                float m = fmaxf(fmaxf(wred[0][g], wred[1][g]),
                                fmaxf(wred[2][g], wred[3][g]));
                int e   = ilogbf(m);
                float s = __int_as_float((unsigned)(127 - e) << 23);  // exact 2^-e
                u[g]  *= s;
                Ce[g] += e;
            }
        }

        pv[w][j] = __floats2bfloat162_rn(u[0], u[1]);
        __syncthreads();
    }

    // finalize: -logZ[b] = -(Ce*ln2 + log(sum_j u[j]*exp(end[j])))
    const float ezj = __expf(endT[j]);
#pragma unroll
    for (int g = 0; g < GG; g++) {
        float z = u[g] * ezj;
        for (int o = 16; o; o >>= 1) z += __shfl_xor_sync(0xffffffffu, z, o);
        if (lane == 0) wred[warp][g] = z;
    }
    __syncthreads();
    if (j < GG) {
        const int g = j;
        float zsum  = wred[0][g] + wred[1][g] + wred[2][g] + wred[3][g];
        double logZ = (double)Ce[g] * 0.6931471805599453 + log((double)zsum);
        g_negLogZ[b0 + g] = (float)(-logZ);
    }
}

// ---- gold-path score + final combine: one block per batch ----
__global__ void __launch_bounds__(128) path_kernel(
    const float* __restrict__ em, const int* __restrict__ tags,
    const float* __restrict__ mask, const float* __restrict__ startT,
    const float* __restrict__ trans, const float* __restrict__ endT,
    float* __restrict__ out)
{
    __shared__ float sacc[4], smsum[4];
    const int b = blockIdx.x, tid = threadIdx.x, warp = tid >> 5, lane = tid & 31;
    float acc = 0.0f, msum = 0.0f;
    for (int t = tid; t < TT; t += 128) {
        int   tg = tags[t * BB + b];
        float m  = mask[t * BB + b];
        acc  += em[(t * BB + b) * KK + tg] * m;
        msum += m;
        if (t > 0) {
            int tp = tags[(t - 1) * BB + b];
            acc += trans[tp * KK + tg] * m;
        }
    }
    for (int o = 16; o; o >>= 1) {
        acc  += __shfl_xor_sync(0xffffffffu, acc, o);
        msum += __shfl_xor_sync(0xffffffffu, msum, o);
    }
    if (lane == 0) { sacc[warp] = acc; smsum[warp] = msum; }
    __syncthreads();
    if (tid == 0) {
        float a  = sacc[0] + sacc[1] + sacc[2] + sacc[3];
        float ms = smsum[0] + smsum[1] + smsum[2] + smsum[3];
        int cnt = (int)(ms + 0.5f); if (cnt < 1) cnt = 1;
        a += startT[tags[b]] + endT[tags[(cnt - 1) * BB + b]];
        atomicAdd(out, a + g_negLogZ[b]);
    }
}

extern "C" void kernel_launch(void* const* d_in, const int* in_sizes, int n_in,
                              void* d_out, int out_size) {
    const float* em     = (const float*)d_in[0];
    const int*   tags   = (const int*)  d_in[1];
    const float* mask   = (const float*)d_in[2];
    const float* startT = (const float*)d_in[3];
    const float* trans  = (const float*)d_in[4];
    const float* endT   = (const float*)d_in[5];
    float* out = (float*)d_out;

    crf_fwd_kernel<<<BB / GG, KK>>>(em, mask, startT, trans, endT, out);
    path_kernel<<<BB, 128>>>(em, tags, mask, startT, trans, endT, out);
}

// round 10
// speedup vs baseline: 1.8865x; 1.0194x over previous
#include <cuda_runtime.h>
#include <cuda_bf16.h>
#include <math.h>

#define TT 1024
#define BB 512
#define KK 128
#define GG 2   // batches per block

__device__ float g_negLogZ[BB];   // -logZ per batch (fwd writes, path reads)

// ---- forward recurrence: scaled linear domain, bf16x2 matvec (lanes = i-pairs) ----
// grid = BB/GG = 256 blocks, 128 threads, 2 CTAs/SM.
__global__ void __launch_bounds__(128, 2) crf_fwd_kernel(
    const float* __restrict__ em,      // [T,B,K]
    const float* __restrict__ mask,    // [T,B]
    const float* __restrict__ startT,  // [K]
    const float* __restrict__ trans,   // [K,K]
    const float* __restrict__ endT,    // [K]
    float* __restrict__ out)
{
    __shared__ alignas(16) __nv_bfloat16 pv[2][GG][KK];  // [buf][batch][i]
    __shared__ float wred[4][GG];

    const int j    = threadIdx.x;   // tag column owned by this thread
    const int warp = j >> 5;
    const int lane = j & 31;
    const int b0   = blockIdx.x * GG;

    if (blockIdx.x == 0 && j == 0) out[0] = 0.0f;  // zero for launch-2 atomics

    // E column packed over i-pairs: epk[m] = (E[2m][j], E[2m+1][j])  -> 64 regs
    __nv_bfloat162 epk[KK / 2];
#pragma unroll
    for (int m = 0; m < KK / 2; m++) {
        epk[m] = __floats2bfloat162_rn(__expf(trans[(2 * m) * KK + j]),
                                       __expf(trans[(2 * m + 1) * KK + j]));
    }

    float u[GG];     // fp32 master state for column j
    int   Ce[GG];    // exact power-of-2 scale exponent
    const float sj = startT[j];
#pragma unroll
    for (int g = 0; g < GG; g++) {
        u[g]  = __expf(sj + em[(b0 + g) * KK + j]);
        Ce[g] = 0;
        pv[1][g][j] = __float2bfloat16(u[g]);   // step t=1 reads buffer 1
    }
    __syncthreads();

    // 2-deep register prefetch pipeline for em/mask
    float ecur[GG], enext[GG], mcur[GG], mnext[GG];
#pragma unroll
    for (int g = 0; g < GG; g++) {
        ecur[g]  = __ldg(&em[(1 * BB + b0 + g) * KK + j]);
        mcur[g]  = __ldg(&mask[1 * BB + b0 + g]);
        enext[g] = __ldg(&em[(2 * BB + b0 + g) * KK + j]);
        mnext[g] = __ldg(&mask[2 * BB + b0 + g]);
    }

    for (int t = 1; t < TT; t++) {
        const int r = t & 1, w = r ^ 1;

        // exp(em) early: MUFU latency hides under the matvec
        float ex[GG];
#pragma unroll
        for (int g = 0; g < GG; g++) ex[g] = __expf(ecur[g]);

        // kick off loads for t+2 (clamped; tail values discarded)
        const int tp = (t + 2 < TT) ? (t + 2) : (TT - 1);
        float epre[GG], mpre[GG];
#pragma unroll
        for (int g = 0; g < GG; g++) {
            epre[g] = __ldg(&em[(tp * BB + b0 + g) * KK + j]);
            mpre[g] = __ldg(&mask[tp * BB + b0 + g]);
        }

        // matvec: S[g] = sum_i u_prev[g][i] * E[i][j]
        // lanes carry (even i, odd i); 4 independent acc chains (2 per batch)
        __nv_bfloat162 a0[GG], a1[GG];
        const __nv_bfloat162 z2 = __float2bfloat162_rn(0.0f);
#pragma unroll
        for (int g = 0; g < GG; g++) { a0[g] = z2; a1[g] = z2; }
#pragma unroll
        for (int k = 0; k < KK / 8; k++) {
#pragma unroll
            for (int g = 0; g < GG; g++) {
                const uint4 q = *(const uint4*)&pv[r][g][8 * k];   // LDS.128 bcast: 8 i's
                a0[g] = __hfma2(epk[4 * k],     *(const __nv_bfloat162*)&q.x, a0[g]);
                a1[g] = __hfma2(epk[4 * k + 1], *(const __nv_bfloat162*)&q.y, a1[g]);
                a0[g] = __hfma2(epk[4 * k + 2], *(const __nv_bfloat162*)&q.z, a0[g]);
                a1[g] = __hfma2(epk[4 * k + 3], *(const __nv_bfloat162*)&q.w, a1[g]);
            }
        }

#pragma unroll
        for (int g = 0; g < GG; g++) {
            const __nv_bfloat162 s2 = __hadd2(a0[g], a1[g]);
            const float S = __low2float(s2) + __high2float(s2);
            const float un = ex[g] * S;
            u[g] = (mcur[g] != 0.0f) ? un : u[g];
        }

        // rotate prefetch pipeline
#pragma unroll
        for (int g = 0; g < GG; g++) {
            ecur[g]  = enext[g];  mcur[g]  = mnext[g];
            enext[g] = epre[g];   mnext[g] = mpre[g];
        }

        // exact power-of-2 rescale every 8 steps
        if ((t & 7) == 0) {
            float wm[GG];
#pragma unroll
            for (int g = 0; g < GG; g++) {
                float v = u[g];
                for (int o = 16; o; o >>= 1) v = fmaxf(v, __shfl_xor_sync(0xffffffffu, v, o));
                wm[g] = v;
            }
            if (lane == 0) {
#pragma unroll
                for (int g = 0; g < GG; g++) wred[warp][g] = wm[g];
            }
            __syncthreads();
#pragma unroll
            for (int g = 0; g < GG; g++) {
                float m = fmaxf(fmaxf(wred[0][g], wred[1][g]),
                                fmaxf(wred[2][g], wred[3][g]));
                int e   = ilogbf(m);
                float s = __int_as_float((unsigned)(127 - e) << 23);  // exact 2^-e
                u[g]  *= s;
                Ce[g] += e;
            }
        }

#pragma unroll
        for (int g = 0; g < GG; g++) pv[w][g][j] = __float2bfloat16(u[g]);
        __syncthreads();
    }

    // finalize: -logZ[b] = -(Ce*ln2 + log(sum_j u[j]*exp(end[j])))
    const float ezj = __expf(endT[j]);
#pragma unroll
    for (int g = 0; g < GG; g++) {
        float z = u[g] * ezj;
        for (int o = 16; o; o >>= 1) z += __shfl_xor_sync(0xffffffffu, z, o);
        if (lane == 0) wred[warp][g] = z;
    }
    __syncthreads();
    if (j < GG) {
        const int g = j;
        float zsum  = wred[0][g] + wred[1][g] + wred[2][g] + wred[3][g];
        double logZ = (double)Ce[g] * 0.6931471805599453 + log((double)zsum);
        g_negLogZ[b0 + g] = (float)(-logZ);
    }
}

// ---- gold-path score + final combine: one block per batch ----
__global__ void __launch_bounds__(128) path_kernel(
    const float* __restrict__ em, const int* __restrict__ tags,
    const float* __restrict__ mask, const float* __restrict__ startT,
    const float* __restrict__ trans, const float* __restrict__ endT,
    float* __restrict__ out)
{
    __shared__ float sacc[4], smsum[4];
    const int b = blockIdx.x, tid = threadIdx.x, warp = tid >> 5, lane = tid & 31;
    float acc = 0.0f, msum = 0.0f;
    for (int t = tid; t < TT; t += 128) {
        int   tg = tags[t * BB + b];
        float m  = mask[t * BB + b];
        acc  += em[(t * BB + b) * KK + tg] * m;
        msum += m;
        if (t > 0) {
            int tp = tags[(t - 1) * BB + b];
            acc += trans[tp * KK + tg] * m;
        }
    }
    for (int o = 16; o; o >>= 1) {
        acc  += __shfl_xor_sync(0xffffffffu, acc, o);
        msum += __shfl_xor_sync(0xffffffffu, msum, o);
    }
    if (lane == 0) { sacc[warp] = acc; smsum[warp] = msum; }
    __syncthreads();
    if (tid == 0) {
        float a  = sacc[0] + sacc[1] + sacc[2] + sacc[3];
        float ms = smsum[0] + smsum[1] + smsum[2] + smsum[3];
        int cnt = (int)(ms + 0.5f); if (cnt < 1) cnt = 1;
        a += startT[tags[b]] + endT[tags[(cnt - 1) * BB + b]];
        atomicAdd(out, a + g_negLogZ[b]);
    }
}

extern "C" void kernel_launch(void* const* d_in, const int* in_sizes, int n_in,
                              void* d_out, int out_size) {
    const float* em     = (const float*)d_in[0];
    const int*   tags   = (const int*)  d_in[1];
    const float* mask   = (const float*)d_in[2];
    const float* startT = (const float*)d_in[3];
    const float* trans  = (const float*)d_in[4];
    const float* endT   = (const float*)d_in[5];
    float* out = (float*)d_out;

    crf_fwd_kernel<<<BB / GG, KK>>>(em, mask, startT, trans, endT, out);
    path_kernel<<<BB, 128>>>(em, tags, mask, startT, trans, endT, out);
}